// round 15
// baseline (speedup 1.0000x reference)
#include <cuda_runtime.h>
#include <cstdint>

// Problem constants (match reference)
#define NN   30000
#define EE   300000
#define NG   512
#define HID  600
#define INF  9
#define NT   128
#define CHID 256
#define KP2  (HID / 2)        // 300 pair-words per row
#define WSZ  (KP2 * HID)      // 180000 words per packed weight

// ---------------- device scratch (allocation-free rule: device globals) ----
__device__ float g_h[NN * HID];
__device__ float g_agg9[NN * INF];
__device__ float g_feats[NG * HID];
__device__ float g_z1[NG * CHID];
__device__ float g_z2[NG * CHID];
__device__ uint32_t g_aggh[NN * KP2];
__device__ uint32_t g_aggl[NN * KP2];
__device__ uint32_t g_t1h[NN * KP2];
__device__ uint32_t g_t1l[NN * KP2];
__device__ uint32_t g_wh[9 * WSZ];
__device__ uint32_t g_wl[9 * WSZ];

__device__ int g_src[EE];
__device__ int g_dst[EE];
__device__ int g_batch[NN];
__device__ int g_deg[NN];
__device__ int g_rowptr[NN + 1];
__device__ int g_cursor[NN];
__device__ int g_col[EE];
__device__ int g_gptr[NG + 1];
__device__ int g_is64;

// fp16 conversions via PTX (avoids cuda_fp16.h)
__device__ __forceinline__ void pack_pair(float v0, float v1,
                                          uint32_t& wh, uint32_t& wl) {
    unsigned short h0, h1, l0, l1;
    float b0, b1;
    asm("cvt.rn.f16.f32 %0, %1;" : "=h"(h0) : "f"(v0));
    asm("cvt.rn.f16.f32 %0, %1;" : "=h"(h1) : "f"(v1));
    asm("cvt.f32.f16 %0, %1;" : "=f"(b0) : "h"(h0));
    asm("cvt.f32.f16 %0, %1;" : "=f"(b1) : "h"(h1));
    float r0 = v0 - b0, r1 = v1 - b1;
    asm("cvt.rn.f16.f32 %0, %1;" : "=h"(l0) : "f"(r0));
    asm("cvt.rn.f16.f32 %0, %1;" : "=h"(l1) : "f"(r1));
    wh = (uint32_t)h0 | ((uint32_t)h1 << 16);
    wl = (uint32_t)l0 | ((uint32_t)l1 << 16);
}

__device__ __forceinline__ uint32_t smem_u32(const void* p) {
    uint32_t a;
    asm("{ .reg .u64 t; cvta.to.shared.u64 t, %1; cvt.u32.u64 %0, t; }"
        : "=r"(a) : "l"(p));
    return a;
}
#define CP_ASYNC4(dst, src, sz) \
    asm volatile("cp.async.ca.shared.global [%0], [%1], 4, %2;" \
                 :: "r"(dst), "l"(src), "r"(sz) : "memory")
#define CP_ASYNC16(dst, src, sz) \
    asm volatile("cp.async.cg.shared.global [%0], [%1], 16, %2;" \
                 :: "r"(dst), "l"(src), "r"(sz) : "memory")
#define CP_COMMIT() asm volatile("cp.async.commit_group;" ::: "memory")
#define CP_WAIT0()  asm volatile("cp.async.wait_group 0;" ::: "memory")

// ---------------- index dtype detection + conversion ----------------------
__global__ void k_detect(const unsigned long long* __restrict__ p) {
    if (threadIdx.x == 0 && blockIdx.x == 0) {
        int is64 = 1;
        for (int i = 0; i < 256; i++)
            if (p[i] >> 32) { is64 = 0; break; }
        g_is64 = is64;
    }
}

__global__ void k_convert(const void* __restrict__ edges,
                          const void* __restrict__ batch) {
    int i = blockIdx.x * blockDim.x + threadIdx.x;
    int is64 = g_is64;
    if (i < EE) {
        if (is64) {
            const long long* p = (const long long*)edges;
            g_src[i] = (int)p[i];
            g_dst[i] = (int)p[EE + i];
        } else {
            const int* p = (const int*)edges;
            g_src[i] = p[i];
            g_dst[i] = p[EE + i];
        }
    }
    if (i < NN) {
        if (is64) {
            const long long* p = (const long long*)batch;
            g_batch[i] = (int)p[i];
        } else {
            const int* p = (const int*)batch;
            g_batch[i] = p[i];
        }
    }
}

// ---------------- weight pre-packing ---------------------------------------
__global__ void k_convw(const float* __restrict__ w, uint32_t* __restrict__ wh,
                        uint32_t* __restrict__ wl) {
    int idx = blockIdx.x * blockDim.x + threadIdx.x;   // 0..WSZ-1
    if (idx >= WSZ) return;
    int kp = idx / HID, n = idx - kp * HID;
    float v0 = w[(2 * kp) * HID + n];
    float v1 = w[(2 * kp + 1) * HID + n];
    uint32_t a, b;
    pack_pair(v0, v1, a, b);
    wh[idx] = a;
    wl[idx] = b;
}

// ---------------- small utility kernels ------------------------------------
__global__ void k_zero_int(int* p, int n) {
    int i = blockIdx.x * blockDim.x + threadIdx.x;
    if (i < n) p[i] = 0;
}

// ---------------- CSR build (dst-major) ------------------------------------
__global__ void k_count(const int* __restrict__ dst, int* __restrict__ deg) {
    int i = blockIdx.x * blockDim.x + threadIdx.x;
    if (i < EE) atomicAdd(&deg[dst[i]], 1);
}

// single-block shuffle scan; writes rowptr AND cursor
__global__ void k_scan(const int* __restrict__ in, int* __restrict__ out,
                       int* __restrict__ cursor, int n) {
    __shared__ int wsum[32];
    __shared__ int s_carry;
    int tid = threadIdx.x, lane = tid & 31, wid = tid >> 5;
    if (tid == 0) s_carry = 0;
    __syncthreads();
    for (int base = 0; base < n; base += 1024) {
        int i = base + tid;
        int v = (i < n) ? in[i] : 0;
        int x = v;
#pragma unroll
        for (int o = 1; o < 32; o <<= 1) {
            int t = __shfl_up_sync(0xffffffffu, x, o);
            if (lane >= o) x += t;
        }
        if (lane == 31) wsum[wid] = x;
        __syncthreads();
        if (wid == 0) {
            int y = wsum[lane];
#pragma unroll
            for (int o = 1; o < 32; o <<= 1) {
                int t = __shfl_up_sync(0xffffffffu, y, o);
                if (lane >= o) y += t;
            }
            wsum[lane] = y;
        }
        __syncthreads();
        int woff = (wid > 0) ? wsum[wid - 1] : 0;
        int incl = x + woff + s_carry;
        if (i < n) { out[i] = incl - v; cursor[i] = incl - v; }
        __syncthreads();
        if (tid == 1023) s_carry = incl;
        __syncthreads();
    }
    if (tid == 0) out[n] = s_carry;
}

__global__ void k_fill(const int* __restrict__ src, const int* __restrict__ dst,
                       int* __restrict__ cursor, int* __restrict__ col) {
    int i = blockIdx.x * blockDim.x + threadIdx.x;
    if (i < EE) {
        int p = atomicAdd(&cursor[dst[i]], 1);
        col[p] = src[i];
    }
}

// ---------------- graph ranges (batch_ind is sorted) -----------------------
__global__ void k_gptr(const int* __restrict__ batch, int* __restrict__ gptr) {
    int g = blockIdx.x * blockDim.x + threadIdx.x;
    if (g > NG) return;
    int lo = 0, hi = NN;
    while (lo < hi) {
        int mid = (lo + hi) >> 1;
        if (batch[mid] < g) lo = mid + 1; else hi = mid;
    }
    gptr[g] = lo;
}

// ---------------- aggregation ----------------------------------------------
__global__ void k_aggregate(const float* __restrict__ h, float* __restrict__ agg,
                            const int* __restrict__ rowptr,
                            const int* __restrict__ col, int width) {
    __shared__ int s_nbr[64];
    int node = blockIdx.x;
    int f = threadIdx.x;
    int CH = (blockDim.x < 64) ? blockDim.x : 64;
    int start = rowptr[node], end = rowptr[node + 1];
    float acc = (f < width) ? h[node * width + f] : 0.f;
    for (int base = start; base < end; base += CH) {
        int cnt = end - base;
        if (cnt > CH) cnt = CH;
        if ((int)threadIdx.x < cnt) s_nbr[threadIdx.x] = col[base + threadIdx.x];
        __syncthreads();
        if (f < width) {
            for (int j = 0; j < cnt; j++)
                acc += h[s_nbr[j] * width + f];
        }
        __syncthreads();
    }
    if (f < width) agg[node * width + f] = acc;
}

__global__ void k_aggregate_pk(const float* __restrict__ h,
                               uint32_t* __restrict__ aggh,
                               uint32_t* __restrict__ aggl,
                               const int* __restrict__ rowptr,
                               const int* __restrict__ col) {
    __shared__ int s_nbr[32];
    int node = blockIdx.x;
    int f4 = threadIdx.x;                  // 0..159, use first 150
    int start = rowptr[node], end = rowptr[node + 1];
    const float4* hv = (const float4*)h;
    float4 acc;
    if (f4 < 150) acc = hv[node * 150 + f4];
    else acc = make_float4(0.f, 0.f, 0.f, 0.f);
    for (int base = start; base < end; base += 32) {
        int cnt = end - base;
        if (cnt > 32) cnt = 32;
        if ((int)threadIdx.x < cnt) s_nbr[threadIdx.x] = col[base + threadIdx.x];
        __syncthreads();
        if (f4 < 150) {
            for (int j = 0; j < cnt; j++) {
                float4 v = hv[s_nbr[j] * 150 + f4];
                acc.x += v.x; acc.y += v.y; acc.z += v.z; acc.w += v.w;
            }
        }
        __syncthreads();
    }
    if (f4 < 150) {
        uint32_t h0, l0, h1, l1;
        pack_pair(acc.x, acc.y, h0, l0);
        pack_pair(acc.z, acc.w, h1, l1);
        int off = node * KP2 + 2 * f4;
        *(uint2*)&aggh[off] = make_uint2(h0, h1);
        *(uint2*)&aggl[off] = make_uint2(l0, l1);
    }
}

// ---------------- pooling (segmented, no atomics) --------------------------
__global__ void k_pool2(const float* __restrict__ h, const int* __restrict__ gptr,
                        float* __restrict__ feats) {
    int g = blockIdx.x;
    int f4 = threadIdx.x;
    if (f4 >= 150) return;
    int start = gptr[g], end = gptr[g + 1];
    const float4* hv = (const float4*)h;
    float4 acc = make_float4(0.f, 0.f, 0.f, 0.f);
    for (int n = start; n < end; n++) {
        float4 v = hv[n * 150 + f4];
        acc.x += v.x; acc.y += v.y; acc.z += v.z; acc.w += v.w;
    }
    ((float4*)feats)[g * 150 + f4] = acc;
}

// ---------------- FFMA SGEMM (layer0 K=9, classifier; optional packed out) --
#define BM 128
#define BN 128
#define BK 8

__global__ __launch_bounds__(256)
void k_sgemm(int M, int N, int K,
             const float* __restrict__ A, const float* __restrict__ B,
             const float* __restrict__ bias, float* __restrict__ C,
             uint32_t* __restrict__ Ch, uint32_t* __restrict__ Cl,
             int relu, int packout) {
    __shared__ float As[BK][BM + 4];
    __shared__ float Bs[BK][BN];

    int tid = threadIdx.x;
    int tx = tid & 15;
    int ty = tid >> 4;
    int m0 = blockIdx.y * BM;
    int n0 = blockIdx.x * BN;

    float acc[8][8];
#pragma unroll
    for (int i = 0; i < 8; i++)
#pragma unroll
        for (int j = 0; j < 8; j++) acc[i][j] = 0.f;

    for (int k0 = 0; k0 < K; k0 += BK) {
#pragma unroll
        for (int i = 0; i < 4; i++) {
            int e = tid * 4 + i;
            int m = e >> 3, k = e & 7;
            int gm = m0 + m, gk = k0 + k;
            As[k][m] = (gm < M && gk < K) ? A[gm * K + gk] : 0.f;
        }
#pragma unroll
        for (int i = 0; i < 4; i++) {
            int e = tid * 4 + i;
            int k = e >> 7, n = e & 127;
            int gn = n0 + n, gk = k0 + k;
            Bs[k][n] = (gn < N && gk < K) ? B[gk * N + gn] : 0.f;
        }
        __syncthreads();

#pragma unroll
        for (int k = 0; k < BK; k++) {
            float4 a0 = *(const float4*)&As[k][ty * 4];
            float4 a1 = *(const float4*)&As[k][64 + ty * 4];
            float4 b0 = *(const float4*)&Bs[k][tx * 4];
            float4 b1 = *(const float4*)&Bs[k][64 + tx * 4];
            float a[8] = {a0.x, a0.y, a0.z, a0.w, a1.x, a1.y, a1.z, a1.w};
            float b[8] = {b0.x, b0.y, b0.z, b0.w, b1.x, b1.y, b1.z, b1.w};
#pragma unroll
            for (int i = 0; i < 8; i++)
#pragma unroll
                for (int j = 0; j < 8; j++)
                    acc[i][j] = fmaf(a[i], b[j], acc[i][j]);
        }
        __syncthreads();
    }

#pragma unroll
    for (int i = 0; i < 8; i++) {
        int r = (i < 4) ? (ty * 4 + i) : (64 + ty * 4 + (i - 4));
        int gm = m0 + r;
        if (gm >= M) continue;
        if (packout) {
#pragma unroll
            for (int j = 0; j < 8; j += 2) {
                int c = (j < 4) ? (tx * 4 + j) : (64 + tx * 4 + (j - 4));
                int gn = n0 + c;
                if (gn >= N) continue;
                float v0 = acc[i][j] + bias[gn];
                float v1 = acc[i][j + 1] + bias[gn + 1];
                if (relu) { v0 = fmaxf(v0, 0.f); v1 = fmaxf(v1, 0.f); }
                uint32_t wh, wl;
                pack_pair(v0, v1, wh, wl);
                int p = gm * (N >> 1) + (gn >> 1);
                Ch[p] = wh;
                Cl[p] = wl;
            }
        } else {
#pragma unroll
            for (int j = 0; j < 8; j++) {
                int c = (j < 4) ? (tx * 4 + j) : (64 + tx * 4 + (j - 4));
                int gn = n0 + c;
                if (gn >= N) continue;
                float v = acc[i][j] + bias[gn];
                if (relu) v = fmaxf(v, 0.f);
                C[gm * N + gn] = v;
            }
        }
    }
}

// ---------------- 3xFP16 mma.sync GEMM, cp.async loader --------------------
// D = act(A @ B + bias). A, B pre-packed pair hi/lo arrays. Loader uses
// cp.async (LDGSTS) issued right after buffer handoff, overlapping the full
// compute phase; guards via src-size (0 = zero-fill).
#define GBM 128
#define GBN 128
#define GBK 16
#define PST 136
#define REGW (8 * PST)
#define BUFW (4 * REGW)
#define OA_HI 0
#define OA_LO REGW
#define OB_HI (2 * REGW)
#define OB_LO (3 * REGW)

__device__ __forceinline__ void mma_f16(float* d, const uint32_t* a,
                                        uint32_t b0, uint32_t b1) {
    asm volatile(
        "mma.sync.aligned.m16n8k16.row.col.f32.f16.f16.f32 "
        "{%0,%1,%2,%3}, {%4,%5,%6,%7}, {%8,%9}, {%0,%1,%2,%3};\n"
        : "+f"(d[0]), "+f"(d[1]), "+f"(d[2]), "+f"(d[3])
        : "r"(a[0]), "r"(a[1]), "r"(a[2]), "r"(a[3]), "r"(b0), "r"(b1));
}

__global__ __launch_bounds__(256, 2)
void k_gemm_f16(int M, int N, int K,
                const uint32_t* __restrict__ Ah, const uint32_t* __restrict__ Al,
                const uint32_t* __restrict__ Bh, const uint32_t* __restrict__ Bl,
                const float* __restrict__ bias,
                float* __restrict__ C,
                uint32_t* __restrict__ Ch, uint32_t* __restrict__ Cl,
                int relu, int packout) {
    __shared__ uint32_t sh[2][BUFW];

    int KPa = K >> 1;                 // pair rows
    int tid = threadIdx.x;
    int lane = tid & 31;
    int warp = tid >> 5;
    int wm = (warp >> 1) * 32;
    int wn = (warp & 1) * 64;
    int lq = lane >> 2;
    int lr = lane & 3;

    int m0 = blockIdx.y * GBM;
    int n0 = blockIdx.x * GBN;

    // A loader: row am, 4 pair-words starting at tile pair-row akp
    int am = tid >> 1;
    int akp = (tid & 1) * 4;
    int gmA = m0 + am;
    bool a_ok = (gmA < M);
    // B loader: pair-row kb (0..7), 4 n-words at nb
    int kb = tid >> 5;
    int nb = (tid & 31) * 4;

    uint32_t sbase = smem_u32(&sh[0][0]);

    float acc[2][8][4];
#pragma unroll
    for (int i = 0; i < 2; i++)
#pragma unroll
        for (int j = 0; j < 8; j++)
#pragma unroll
            for (int c = 0; c < 4; c++) acc[i][j][c] = 0.f;

    int NIT = (K + GBK - 1) / GBK;

    // ---- prologue: async-load tile 0 into buffer 0 ----
    {
        uint32_t dbase = sbase;
        int pk0 = akp;
#pragma unroll
        for (int i = 0; i < 4; i++) {
            int ok = (a_ok && (pk0 + i) < KPa) ? 4 : 0;
            const uint32_t* sA = ok ? (Ah + (size_t)gmA * KPa + pk0 + i) : Ah;
            const uint32_t* sL = ok ? (Al + (size_t)gmA * KPa + pk0 + i) : Al;
            CP_ASYNC4(dbase + (uint32_t)(OA_HI + (akp + i) * PST + am) * 4u, sA, ok);
            CP_ASYNC4(dbase + (uint32_t)(OA_LO + (akp + i) * PST + am) * 4u, sL, ok);
        }
        int kpg = kb;
        int gn = n0 + nb;
        int okb = ((kpg < KPa) && (gn + 4 <= N)) ? 16 : 0;
        const uint32_t* sB = okb ? (Bh + (size_t)kpg * N + gn) : Bh;
        const uint32_t* sBl = okb ? (Bl + (size_t)kpg * N + gn) : Bl;
        CP_ASYNC16(dbase + (uint32_t)(OB_HI + kb * PST + nb) * 4u, sB, okb);
        CP_ASYNC16(dbase + (uint32_t)(OB_LO + kb * PST + nb) * 4u, sBl, okb);
    }
    CP_COMMIT();

    int buf_i = 0;
    for (int it = 0; it < NIT; it++) {
        CP_WAIT0();
        __syncthreads();

        // ---- issue next tile's async copies into the other buffer ----
        if (it + 1 < NIT) {
            uint32_t dbase = sbase + (uint32_t)(buf_i ^ 1) * (BUFW * 4u);
            int pk0 = (it + 1) * 8 + akp;
#pragma unroll
            for (int i = 0; i < 4; i++) {
                int ok = (a_ok && (pk0 + i) < KPa) ? 4 : 0;
                const uint32_t* sA = ok ? (Ah + (size_t)gmA * KPa + pk0 + i) : Ah;
                const uint32_t* sL = ok ? (Al + (size_t)gmA * KPa + pk0 + i) : Al;
                CP_ASYNC4(dbase + (uint32_t)(OA_HI + (akp + i) * PST + am) * 4u, sA, ok);
                CP_ASYNC4(dbase + (uint32_t)(OA_LO + (akp + i) * PST + am) * 4u, sL, ok);
            }
            int kpg = (it + 1) * 8 + kb;
            int gn = n0 + nb;
            int okb = ((kpg < KPa) && (gn + 4 <= N)) ? 16 : 0;
            const uint32_t* sB = okb ? (Bh + (size_t)kpg * N + gn) : Bh;
            const uint32_t* sBl = okb ? (Bl + (size_t)kpg * N + gn) : Bl;
            CP_ASYNC16(dbase + (uint32_t)(OB_HI + kb * PST + nb) * 4u, sB, okb);
            CP_ASYNC16(dbase + (uint32_t)(OB_LO + kb * PST + nb) * 4u, sBl, okb);
        }
        CP_COMMIT();

        // ---- compute on current buffer ----
        const uint32_t* bufc = sh[buf_i];
        uint32_t ah[2][4], al[2][4];
#pragma unroll
        for (int i = 0; i < 2; i++) {
            int r1 = wm + i * 16 + lq;
            ah[i][0] = bufc[OA_HI + lr * PST + r1];
            ah[i][1] = bufc[OA_HI + lr * PST + r1 + 8];
            ah[i][2] = bufc[OA_HI + (lr + 4) * PST + r1];
            ah[i][3] = bufc[OA_HI + (lr + 4) * PST + r1 + 8];
            al[i][0] = bufc[OA_LO + lr * PST + r1];
            al[i][1] = bufc[OA_LO + lr * PST + r1 + 8];
            al[i][2] = bufc[OA_LO + (lr + 4) * PST + r1];
            al[i][3] = bufc[OA_LO + (lr + 4) * PST + r1 + 8];
        }
#pragma unroll
        for (int j = 0; j < 8; j++) {
            int n = wn + j * 8 + lq;
            uint32_t bh0 = bufc[OB_HI + lr * PST + n];
            uint32_t bh1 = bufc[OB_HI + (lr + 4) * PST + n];
            uint32_t bl0 = bufc[OB_LO + lr * PST + n];
            uint32_t bl1 = bufc[OB_LO + (lr + 4) * PST + n];
            mma_f16(acc[0][j], ah[0], bh0, bh1);
            mma_f16(acc[1][j], ah[1], bh0, bh1);
            mma_f16(acc[0][j], ah[0], bl0, bl1);
            mma_f16(acc[1][j], ah[1], bl0, bl1);
            mma_f16(acc[0][j], al[0], bh0, bh1);
            mma_f16(acc[1][j], al[1], bh0, bh1);
        }
        buf_i ^= 1;
    }

    // ---- epilogue ----
    int lr2 = 2 * lr;
    if (packout) {
        int NP = N >> 1;
#pragma unroll
        for (int i = 0; i < 2; i++) {
            int colp = n0 + wn + lr2;
#pragma unroll
            for (int j = 0; j < 8; j++) {
                int col = colp + j * 8;
                if (col >= N) continue;
                int pidx = col >> 1;
                float bi0 = bias[col], bi1 = bias[col + 1];
                int r0 = m0 + wm + i * 16 + lq;
                if (r0 < M) {
                    float v0 = acc[i][j][0] + bi0;
                    float v1 = acc[i][j][1] + bi1;
                    if (relu) { v0 = fmaxf(v0, 0.f); v1 = fmaxf(v1, 0.f); }
                    uint32_t wh, wl;
                    pack_pair(v0, v1, wh, wl);
                    Ch[r0 * NP + pidx] = wh;
                    Cl[r0 * NP + pidx] = wl;
                }
                int r1 = r0 + 8;
                if (r1 < M) {
                    float v0 = acc[i][j][2] + bi0;
                    float v1 = acc[i][j][3] + bi1;
                    if (relu) { v0 = fmaxf(v0, 0.f); v1 = fmaxf(v1, 0.f); }
                    uint32_t wh, wl;
                    pack_pair(v0, v1, wh, wl);
                    Ch[r1 * NP + pidx] = wh;
                    Cl[r1 * NP + pidx] = wl;
                }
            }
        }
    } else {
#pragma unroll
        for (int i = 0; i < 2; i++) {
#pragma unroll
            for (int c = 0; c < 4; c++) {
                int row = m0 + wm + i * 16 + lq + ((c >= 2) ? 8 : 0);
                if (row >= M) continue;
#pragma unroll
                for (int j = 0; j < 8; j++) {
                    int col = n0 + wn + j * 8 + lr2 + (c & 1);
                    if (col >= N) continue;
                    float v = acc[i][j][c] + bias[col];
                    if (relu) v = fmaxf(v, 0.f);
                    C[row * N + col] = v;
                }
            }
        }
    }
}

// ---------------- host orchestration ---------------------------------------
static inline void sgemm(int M, int N, int K, const float* A, const float* B,
                         const float* bias, float* C, uint32_t* Ch, uint32_t* Cl,
                         int relu, int packout) {
    dim3 grid((N + BN - 1) / BN, (M + BM - 1) / BM);
    k_sgemm<<<grid, 256>>>(M, N, K, A, B, bias, C, Ch, Cl, relu, packout);
}

static inline void gemm_f16(int M, int N, int K,
                            const uint32_t* Ah, const uint32_t* Al,
                            const uint32_t* Bh, const uint32_t* Bl,
                            const float* bias, float* C,
                            uint32_t* Ch, uint32_t* Cl, int relu, int packout) {
    dim3 grid((N + GBN - 1) / GBN, (M + GBM - 1) / GBM);
    k_gemm_f16<<<grid, 256>>>(M, N, K, Ah, Al, Bh, Bl, bias, C, Ch, Cl, relu, packout);
}

extern "C" void kernel_launch(void* const* d_in, const int* in_sizes, int n_in,
                              void* d_out, int out_size) {
    const float* x      = (const float*)d_in[0];
    const void*  edges  = d_in[1];
    const void*  batch  = d_in[2];
    const float* w1_0 = (const float*)d_in[3];
    const float* b1_0 = (const float*)d_in[4];
    const float* w2_0 = (const float*)d_in[5];
    const float* b2_0 = (const float*)d_in[6];
    const float* w1_r = (const float*)d_in[7];
    const float* b1_r = (const float*)d_in[8];
    const float* w2_r = (const float*)d_in[9];
    const float* b2_r = (const float*)d_in[10];
    const float* cw1  = (const float*)d_in[11];
    const float* cb1  = (const float*)d_in[12];
    const float* cw2  = (const float*)d_in[13];
    const float* cb2  = (const float*)d_in[14];
    const float* cw3  = (const float*)d_in[15];
    const float* cb3  = (const float*)d_in[16];
    float* out = (float*)d_out;

    float *h, *agg9, *feats, *z1, *z2;
    uint32_t *aggh, *aggl, *t1h, *t1l, *wh, *wl;
    int *src, *dst, *bat, *deg, *rowptr, *cursor, *col, *gptr;
    cudaGetSymbolAddress((void**)&h, g_h);
    cudaGetSymbolAddress((void**)&agg9, g_agg9);
    cudaGetSymbolAddress((void**)&feats, g_feats);
    cudaGetSymbolAddress((void**)&z1, g_z1);
    cudaGetSymbolAddress((void**)&z2, g_z2);
    cudaGetSymbolAddress((void**)&aggh, g_aggh);
    cudaGetSymbolAddress((void**)&aggl, g_aggl);
    cudaGetSymbolAddress((void**)&t1h, g_t1h);
    cudaGetSymbolAddress((void**)&t1l, g_t1l);
    cudaGetSymbolAddress((void**)&wh, g_wh);
    cudaGetSymbolAddress((void**)&wl, g_wl);
    cudaGetSymbolAddress((void**)&src, g_src);
    cudaGetSymbolAddress((void**)&dst, g_dst);
    cudaGetSymbolAddress((void**)&bat, g_batch);
    cudaGetSymbolAddress((void**)&deg, g_deg);
    cudaGetSymbolAddress((void**)&rowptr, g_rowptr);
    cudaGetSymbolAddress((void**)&cursor, g_cursor);
    cudaGetSymbolAddress((void**)&col, g_col);
    cudaGetSymbolAddress((void**)&gptr, g_gptr);

    // 1) index dtype detect + convert
    k_detect<<<1, 32>>>((const unsigned long long*)edges);
    {
        int n = (EE > NN) ? EE : NN;
        k_convert<<<(n + 255) / 256, 256>>>(edges, batch);
    }

    // 2) CSR build + graph ranges + weight packing
    k_zero_int<<<(NN + 255) / 256, 256>>>(deg, NN);
    k_count<<<(EE + 255) / 256, 256>>>(dst, deg);
    k_scan<<<1, 1024>>>(deg, rowptr, cursor, NN);
    k_fill<<<(EE + 255) / 256, 256>>>(src, dst, cursor, col);
    k_gptr<<<(NG + 1 + 255) / 256, 256>>>(bat, gptr);
    {
        int wgrid = (WSZ + 255) / 256;
        k_convw<<<wgrid, 256>>>(w2_0, wh, wl);
        for (int i = 0; i < 4; i++) {
            k_convw<<<wgrid, 256>>>(w1_r + i * HID * HID,
                                    wh + (1 + 2 * i) * WSZ, wl + (1 + 2 * i) * WSZ);
            k_convw<<<wgrid, 256>>>(w2_r + i * HID * HID,
                                    wh + (2 + 2 * i) * WSZ, wl + (2 + 2 * i) * WSZ);
        }
    }

    // 3) layer 0
    k_aggregate<<<NN, 32>>>(x, agg9, rowptr, col, INF);
    sgemm(NN, HID, INF, agg9, w1_0, b1_0, nullptr, t1h, t1l, 1, 1);
    gemm_f16(NN, HID, HID, t1h, t1l, wh, wl, b2_0, h, nullptr, nullptr, 1, 0);

    // 4) layers 1..4
    for (int i = 0; i < 4; i++) {
        k_aggregate_pk<<<NN, 160>>>(h, aggh, aggl, rowptr, col);
        gemm_f16(NN, HID, HID, aggh, aggl,
                 wh + (1 + 2 * i) * WSZ, wl + (1 + 2 * i) * WSZ,
                 b1_r + i * HID, nullptr, t1h, t1l, 1, 1);
        gemm_f16(NN, HID, HID, t1h, t1l,
                 wh + (2 + 2 * i) * WSZ, wl + (2 + 2 * i) * WSZ,
                 b2_r + i * HID, h, nullptr, nullptr, (i < 3) ? 1 : 0, 0);
    }

    // 5) global_add_pool
    k_pool2<<<NG, 160>>>(h, gptr, feats);

    // 6) classifier MLP
    sgemm(NG, CHID, HID, feats, cw1, cb1, z1, nullptr, nullptr, 1, 0);
    sgemm(NG, CHID, CHID, z1, cw2, cb2, z2, nullptr, nullptr, 1, 0);
    sgemm(NG, NT, CHID, z2, cw3, cb3, out, nullptr, nullptr, 0, 0);
}

// round 16
// speedup vs baseline: 1.4216x; 1.4216x over previous
#include <cuda_runtime.h>
#include <cstdint>

// Problem constants (match reference)
#define NN   30000
#define EE   300000
#define NG   512
#define HID  600
#define INF  9
#define NT   128
#define CHID 256
#define KP2  (HID / 2)        // 300 pair-words per row
#define WSZ  (KP2 * HID)      // 180000 words per packed weight

// ---------------- device scratch (allocation-free rule: device globals) ----
__device__ float g_h[NN * HID];
__device__ float g_agg9[NN * INF];
__device__ float g_feats[NG * HID];
__device__ float g_z1[NG * CHID];
__device__ float g_z2[NG * CHID];
__device__ uint32_t g_aggh[NN * KP2];
__device__ uint32_t g_aggl[NN * KP2];
__device__ uint32_t g_t1h[NN * KP2];
__device__ uint32_t g_t1l[NN * KP2];
__device__ uint32_t g_wh[9 * WSZ];
__device__ uint32_t g_wl[9 * WSZ];

__device__ int g_src[EE];
__device__ int g_dst[EE];
__device__ int g_batch[NN];
__device__ int g_deg[NN];
__device__ int g_rowptr[NN + 1];
__device__ int g_cursor[NN];
__device__ int g_col[EE];
__device__ int g_gptr[NG + 1];
__device__ int g_is64;

// fp16 conversions via PTX (avoids cuda_fp16.h)
__device__ __forceinline__ void pack_pair(float v0, float v1,
                                          uint32_t& wh, uint32_t& wl) {
    unsigned short h0, h1, l0, l1;
    float b0, b1;
    asm("cvt.rn.f16.f32 %0, %1;" : "=h"(h0) : "f"(v0));
    asm("cvt.rn.f16.f32 %0, %1;" : "=h"(h1) : "f"(v1));
    asm("cvt.f32.f16 %0, %1;" : "=f"(b0) : "h"(h0));
    asm("cvt.f32.f16 %0, %1;" : "=f"(b1) : "h"(h1));
    float r0 = v0 - b0, r1 = v1 - b1;
    asm("cvt.rn.f16.f32 %0, %1;" : "=h"(l0) : "f"(r0));
    asm("cvt.rn.f16.f32 %0, %1;" : "=h"(l1) : "f"(r1));
    wh = (uint32_t)h0 | ((uint32_t)h1 << 16);
    wl = (uint32_t)l0 | ((uint32_t)l1 << 16);
}

__device__ __forceinline__ uint32_t smem_u32(const void* p) {
    uint32_t a;
    asm("{ .reg .u64 t; cvta.to.shared.u64 t, %1; cvt.u32.u64 %0, t; }"
        : "=r"(a) : "l"(p));
    return a;
}
#define CP_ASYNC16(dst, src, sz) \
    asm volatile("cp.async.cg.shared.global [%0], [%1], 16, %2;" \
                 :: "r"(dst), "l"(src), "r"(sz) : "memory")
#define CP_COMMIT() asm volatile("cp.async.commit_group;" ::: "memory")
#define CP_WAIT0()  asm volatile("cp.async.wait_group 0;" ::: "memory")

// ---------------- index dtype detection + conversion ----------------------
__global__ void k_detect(const unsigned long long* __restrict__ p) {
    if (threadIdx.x == 0 && blockIdx.x == 0) {
        int is64 = 1;
        for (int i = 0; i < 256; i++)
            if (p[i] >> 32) { is64 = 0; break; }
        g_is64 = is64;
    }
}

__global__ void k_convert(const void* __restrict__ edges,
                          const void* __restrict__ batch) {
    int i = blockIdx.x * blockDim.x + threadIdx.x;
    int is64 = g_is64;
    if (i < EE) {
        if (is64) {
            const long long* p = (const long long*)edges;
            g_src[i] = (int)p[i];
            g_dst[i] = (int)p[EE + i];
        } else {
            const int* p = (const int*)edges;
            g_src[i] = p[i];
            g_dst[i] = p[EE + i];
        }
    }
    if (i < NN) {
        if (is64) {
            const long long* p = (const long long*)batch;
            g_batch[i] = (int)p[i];
        } else {
            const int* p = (const int*)batch;
            g_batch[i] = p[i];
        }
    }
}

// ---------------- weight pre-packing ---------------------------------------
__global__ void k_convw(const float* __restrict__ w, uint32_t* __restrict__ wh,
                        uint32_t* __restrict__ wl) {
    int idx = blockIdx.x * blockDim.x + threadIdx.x;   // 0..WSZ-1
    if (idx >= WSZ) return;
    int kp = idx / HID, n = idx - kp * HID;
    float v0 = w[(2 * kp) * HID + n];
    float v1 = w[(2 * kp + 1) * HID + n];
    uint32_t a, b;
    pack_pair(v0, v1, a, b);
    wh[idx] = a;
    wl[idx] = b;
}

// ---------------- small utility kernels ------------------------------------
__global__ void k_zero_int(int* p, int n) {
    int i = blockIdx.x * blockDim.x + threadIdx.x;
    if (i < n) p[i] = 0;
}

// ---------------- CSR build (dst-major) ------------------------------------
__global__ void k_count(const int* __restrict__ dst, int* __restrict__ deg) {
    int i = blockIdx.x * blockDim.x + threadIdx.x;
    if (i < EE) atomicAdd(&deg[dst[i]], 1);
}

// single-block shuffle scan; writes rowptr AND cursor
__global__ void k_scan(const int* __restrict__ in, int* __restrict__ out,
                       int* __restrict__ cursor, int n) {
    __shared__ int wsum[32];
    __shared__ int s_carry;
    int tid = threadIdx.x, lane = tid & 31, wid = tid >> 5;
    if (tid == 0) s_carry = 0;
    __syncthreads();
    for (int base = 0; base < n; base += 1024) {
        int i = base + tid;
        int v = (i < n) ? in[i] : 0;
        int x = v;
#pragma unroll
        for (int o = 1; o < 32; o <<= 1) {
            int t = __shfl_up_sync(0xffffffffu, x, o);
            if (lane >= o) x += t;
        }
        if (lane == 31) wsum[wid] = x;
        __syncthreads();
        if (wid == 0) {
            int y = wsum[lane];
#pragma unroll
            for (int o = 1; o < 32; o <<= 1) {
                int t = __shfl_up_sync(0xffffffffu, y, o);
                if (lane >= o) y += t;
            }
            wsum[lane] = y;
        }
        __syncthreads();
        int woff = (wid > 0) ? wsum[wid - 1] : 0;
        int incl = x + woff + s_carry;
        if (i < n) { out[i] = incl - v; cursor[i] = incl - v; }
        __syncthreads();
        if (tid == 1023) s_carry = incl;
        __syncthreads();
    }
    if (tid == 0) out[n] = s_carry;
}

__global__ void k_fill(const int* __restrict__ src, const int* __restrict__ dst,
                       int* __restrict__ cursor, int* __restrict__ col) {
    int i = blockIdx.x * blockDim.x + threadIdx.x;
    if (i < EE) {
        int p = atomicAdd(&cursor[dst[i]], 1);
        col[p] = src[i];
    }
}

// ---------------- graph ranges (batch_ind is sorted) -----------------------
__global__ void k_gptr(const int* __restrict__ batch, int* __restrict__ gptr) {
    int g = blockIdx.x * blockDim.x + threadIdx.x;
    if (g > NG) return;
    int lo = 0, hi = NN;
    while (lo < hi) {
        int mid = (lo + hi) >> 1;
        if (batch[mid] < g) lo = mid + 1; else hi = mid;
    }
    gptr[g] = lo;
}

// ---------------- aggregation ----------------------------------------------
__global__ void k_aggregate(const float* __restrict__ h, float* __restrict__ agg,
                            const int* __restrict__ rowptr,
                            const int* __restrict__ col, int width) {
    __shared__ int s_nbr[64];
    int node = blockIdx.x;
    int f = threadIdx.x;
    int CH = (blockDim.x < 64) ? blockDim.x : 64;
    int start = rowptr[node], end = rowptr[node + 1];
    float acc = (f < width) ? h[node * width + f] : 0.f;
    for (int base = start; base < end; base += CH) {
        int cnt = end - base;
        if (cnt > CH) cnt = CH;
        if ((int)threadIdx.x < cnt) s_nbr[threadIdx.x] = col[base + threadIdx.x];
        __syncthreads();
        if (f < width) {
            for (int j = 0; j < cnt; j++)
                acc += h[s_nbr[j] * width + f];
        }
        __syncthreads();
    }
    if (f < width) agg[node * width + f] = acc;
}

__global__ void k_aggregate_pk(const float* __restrict__ h,
                               uint32_t* __restrict__ aggh,
                               uint32_t* __restrict__ aggl,
                               const int* __restrict__ rowptr,
                               const int* __restrict__ col) {
    __shared__ int s_nbr[32];
    int node = blockIdx.x;
    int f4 = threadIdx.x;                  // 0..159, use first 150
    int start = rowptr[node], end = rowptr[node + 1];
    const float4* hv = (const float4*)h;
    float4 acc;
    if (f4 < 150) acc = hv[node * 150 + f4];
    else acc = make_float4(0.f, 0.f, 0.f, 0.f);
    for (int base = start; base < end; base += 32) {
        int cnt = end - base;
        if (cnt > 32) cnt = 32;
        if ((int)threadIdx.x < cnt) s_nbr[threadIdx.x] = col[base + threadIdx.x];
        __syncthreads();
        if (f4 < 150) {
            for (int j = 0; j < cnt; j++) {
                float4 v = hv[s_nbr[j] * 150 + f4];
                acc.x += v.x; acc.y += v.y; acc.z += v.z; acc.w += v.w;
            }
        }
        __syncthreads();
    }
    if (f4 < 150) {
        uint32_t h0, l0, h1, l1;
        pack_pair(acc.x, acc.y, h0, l0);
        pack_pair(acc.z, acc.w, h1, l1);
        int off = node * KP2 + 2 * f4;
        *(uint2*)&aggh[off] = make_uint2(h0, h1);
        *(uint2*)&aggl[off] = make_uint2(l0, l1);
    }
}

// ---------------- pooling (segmented, no atomics) --------------------------
__global__ void k_pool2(const float* __restrict__ h, const int* __restrict__ gptr,
                        float* __restrict__ feats) {
    int g = blockIdx.x;
    int f4 = threadIdx.x;
    if (f4 >= 150) return;
    int start = gptr[g], end = gptr[g + 1];
    const float4* hv = (const float4*)h;
    float4 acc = make_float4(0.f, 0.f, 0.f, 0.f);
    for (int n = start; n < end; n++) {
        float4 v = hv[n * 150 + f4];
        acc.x += v.x; acc.y += v.y; acc.z += v.z; acc.w += v.w;
    }
    ((float4*)feats)[g * 150 + f4] = acc;
}

// ---------------- FFMA SGEMM (layer0 K=9, classifier; optional packed out) --
#define BM 128
#define BN 128
#define BK 8

__global__ __launch_bounds__(256)
void k_sgemm(int M, int N, int K,
             const float* __restrict__ A, const float* __restrict__ B,
             const float* __restrict__ bias, float* __restrict__ C,
             uint32_t* __restrict__ Ch, uint32_t* __restrict__ Cl,
             int relu, int packout) {
    __shared__ float As[BK][BM + 4];
    __shared__ float Bs[BK][BN];

    int tid = threadIdx.x;
    int tx = tid & 15;
    int ty = tid >> 4;
    int m0 = blockIdx.y * BM;
    int n0 = blockIdx.x * BN;

    float acc[8][8];
#pragma unroll
    for (int i = 0; i < 8; i++)
#pragma unroll
        for (int j = 0; j < 8; j++) acc[i][j] = 0.f;

    for (int k0 = 0; k0 < K; k0 += BK) {
#pragma unroll
        for (int i = 0; i < 4; i++) {
            int e = tid * 4 + i;
            int m = e >> 3, k = e & 7;
            int gm = m0 + m, gk = k0 + k;
            As[k][m] = (gm < M && gk < K) ? A[gm * K + gk] : 0.f;
        }
#pragma unroll
        for (int i = 0; i < 4; i++) {
            int e = tid * 4 + i;
            int k = e >> 7, n = e & 127;
            int gn = n0 + n, gk = k0 + k;
            Bs[k][n] = (gn < N && gk < K) ? B[gk * N + gn] : 0.f;
        }
        __syncthreads();

#pragma unroll
        for (int k = 0; k < BK; k++) {
            float4 a0 = *(const float4*)&As[k][ty * 4];
            float4 a1 = *(const float4*)&As[k][64 + ty * 4];
            float4 b0 = *(const float4*)&Bs[k][tx * 4];
            float4 b1 = *(const float4*)&Bs[k][64 + tx * 4];
            float a[8] = {a0.x, a0.y, a0.z, a0.w, a1.x, a1.y, a1.z, a1.w};
            float b[8] = {b0.x, b0.y, b0.z, b0.w, b1.x, b1.y, b1.z, b1.w};
#pragma unroll
            for (int i = 0; i < 8; i++)
#pragma unroll
                for (int j = 0; j < 8; j++)
                    acc[i][j] = fmaf(a[i], b[j], acc[i][j]);
        }
        __syncthreads();
    }

#pragma unroll
    for (int i = 0; i < 8; i++) {
        int r = (i < 4) ? (ty * 4 + i) : (64 + ty * 4 + (i - 4));
        int gm = m0 + r;
        if (gm >= M) continue;
        if (packout) {
#pragma unroll
            for (int j = 0; j < 8; j += 2) {
                int c = (j < 4) ? (tx * 4 + j) : (64 + tx * 4 + (j - 4));
                int gn = n0 + c;
                if (gn >= N) continue;
                float v0 = acc[i][j] + bias[gn];
                float v1 = acc[i][j + 1] + bias[gn + 1];
                if (relu) { v0 = fmaxf(v0, 0.f); v1 = fmaxf(v1, 0.f); }
                uint32_t wh, wl;
                pack_pair(v0, v1, wh, wl);
                int p = gm * (N >> 1) + (gn >> 1);
                Ch[p] = wh;
                Cl[p] = wl;
            }
        } else {
#pragma unroll
            for (int j = 0; j < 8; j++) {
                int c = (j < 4) ? (tx * 4 + j) : (64 + tx * 4 + (j - 4));
                int gn = n0 + c;
                if (gn >= N) continue;
                float v = acc[i][j] + bias[gn];
                if (relu) v = fmaxf(v, 0.f);
                C[gm * N + gn] = v;
            }
        }
    }
}

// ---------------- 3xFP16 mma.sync GEMM, 16B cp.async loader ----------------
// D = act(A @ B + bias). A, B pre-packed pair hi/lo arrays (row-major).
// smem A tile stored row-major [am][kp] with stride 12 so the A copy is one
// 16B cp.async per region per thread (gmem and smem both contiguous).
// Fragment LDS banks: (12*lq + lr) mod 32 is a permutation -> conflict-free.
#define GBM 128
#define GBN 128
#define GBK 16
#define ASTW 12                        // A smem stride (words), pad 8->12
#define PST 136                        // B smem stride (words)
#define OAH 0
#define OAL (128 * ASTW)               // 1536
#define OBH (2 * 128 * ASTW)           // 3072
#define OBL (OBH + 8 * PST)            // 4160
#define BUFW (OBL + 8 * PST)           // 5248 words = 21 KB per buffer

__device__ __forceinline__ void mma_f16(float* d, const uint32_t* a,
                                        uint32_t b0, uint32_t b1) {
    asm volatile(
        "mma.sync.aligned.m16n8k16.row.col.f32.f16.f16.f32 "
        "{%0,%1,%2,%3}, {%4,%5,%6,%7}, {%8,%9}, {%0,%1,%2,%3};\n"
        : "+f"(d[0]), "+f"(d[1]), "+f"(d[2]), "+f"(d[3])
        : "r"(a[0]), "r"(a[1]), "r"(a[2]), "r"(a[3]), "r"(b0), "r"(b1));
}

__global__ __launch_bounds__(256, 2)
void k_gemm_f16(int M, int N, int K,
                const uint32_t* __restrict__ Ah, const uint32_t* __restrict__ Al,
                const uint32_t* __restrict__ Bh, const uint32_t* __restrict__ Bl,
                const float* __restrict__ bias,
                float* __restrict__ C,
                uint32_t* __restrict__ Ch, uint32_t* __restrict__ Cl,
                int relu, int packout) {
    __shared__ alignas(16) uint32_t sh[2][BUFW];

    int KPa = K >> 1;                 // pair rows
    int tid = threadIdx.x;
    int lane = tid & 31;
    int warp = tid >> 5;
    int wm = (warp >> 1) * 32;
    int wn = (warp & 1) * 64;
    int lq = lane >> 2;
    int lr = lane & 3;

    int m0 = blockIdx.y * GBM;
    int n0 = blockIdx.x * GBN;

    // A loader: row am, 4 consecutive pair-words at tile pair-row akp
    int am = tid >> 1;
    int akp = (tid & 1) * 4;
    int gmA = m0 + am;
    bool a_ok = (gmA < M);
    // B loader: pair-row kb (0..7), 4 n-words at nb
    int kb = tid >> 5;
    int nb = (tid & 31) * 4;

    uint32_t sbase = smem_u32(&sh[0][0]);
    uint32_t a_dst = (uint32_t)(OAH + am * ASTW + akp) * 4u;
    uint32_t al_dst = (uint32_t)(OAL + am * ASTW + akp) * 4u;
    uint32_t bh_dst = (uint32_t)(OBH + kb * PST + nb) * 4u;
    uint32_t bl_dst = (uint32_t)(OBL + kb * PST + nb) * 4u;

    float acc[2][8][4];
#pragma unroll
    for (int i = 0; i < 2; i++)
#pragma unroll
        for (int j = 0; j < 8; j++)
#pragma unroll
            for (int c = 0; c < 4; c++) acc[i][j][c] = 0.f;

    int NIT = (K + GBK - 1) / GBK;

    // ---- prologue: async-load tile 0 into buffer 0 ----
    {
        int pk0 = akp;
        int oka = (a_ok && pk0 + 4 <= KPa) ? 16 : 0;
        const uint32_t* sA = oka ? (Ah + (size_t)gmA * KPa + pk0) : Ah;
        const uint32_t* sL = oka ? (Al + (size_t)gmA * KPa + pk0) : Al;
        CP_ASYNC16(sbase + a_dst, sA, oka);
        CP_ASYNC16(sbase + al_dst, sL, oka);
        int kpg = kb;
        int gn = n0 + nb;
        int okb = ((kpg < KPa) && (gn + 4 <= N)) ? 16 : 0;
        const uint32_t* sB = okb ? (Bh + (size_t)kpg * N + gn) : Bh;
        const uint32_t* sBl = okb ? (Bl + (size_t)kpg * N + gn) : Bl;
        CP_ASYNC16(sbase + bh_dst, sB, okb);
        CP_ASYNC16(sbase + bl_dst, sBl, okb);
    }
    CP_COMMIT();

    int buf_i = 0;
    for (int it = 0; it < NIT; it++) {
        CP_WAIT0();
        __syncthreads();

        // ---- issue next tile's async copies into the other buffer ----
        if (it + 1 < NIT) {
            uint32_t dbase = sbase + (uint32_t)(buf_i ^ 1) * (BUFW * 4u);
            int pk0 = (it + 1) * 8 + akp;
            int oka = (a_ok && pk0 + 4 <= KPa) ? 16 : 0;
            const uint32_t* sA = oka ? (Ah + (size_t)gmA * KPa + pk0) : Ah;
            const uint32_t* sL = oka ? (Al + (size_t)gmA * KPa + pk0) : Al;
            CP_ASYNC16(dbase + a_dst, sA, oka);
            CP_ASYNC16(dbase + al_dst, sL, oka);
            int kpg = (it + 1) * 8 + kb;
            int gn = n0 + nb;
            int okb = ((kpg < KPa) && (gn + 4 <= N)) ? 16 : 0;
            const uint32_t* sB = okb ? (Bh + (size_t)kpg * N + gn) : Bh;
            const uint32_t* sBl = okb ? (Bl + (size_t)kpg * N + gn) : Bl;
            CP_ASYNC16(dbase + bh_dst, sB, okb);
            CP_ASYNC16(dbase + bl_dst, sBl, okb);
        }
        CP_COMMIT();

        // ---- compute on current buffer ----
        const uint32_t* bufc = sh[buf_i];
        uint32_t ah[2][4], al[2][4];
#pragma unroll
        for (int i = 0; i < 2; i++) {
            int r1 = wm + i * 16 + lq;
            ah[i][0] = bufc[OAH + r1 * ASTW + lr];
            ah[i][1] = bufc[OAH + (r1 + 8) * ASTW + lr];
            ah[i][2] = bufc[OAH + r1 * ASTW + lr + 4];
            ah[i][3] = bufc[OAH + (r1 + 8) * ASTW + lr + 4];
            al[i][0] = bufc[OAL + r1 * ASTW + lr];
            al[i][1] = bufc[OAL + (r1 + 8) * ASTW + lr];
            al[i][2] = bufc[OAL + r1 * ASTW + lr + 4];
            al[i][3] = bufc[OAL + (r1 + 8) * ASTW + lr + 4];
        }
#pragma unroll
        for (int j = 0; j < 8; j++) {
            int n = wn + j * 8 + lq;
            uint32_t bh0 = bufc[OBH + lr * PST + n];
            uint32_t bh1 = bufc[OBH + (lr + 4) * PST + n];
            uint32_t bl0 = bufc[OBL + lr * PST + n];
            uint32_t bl1 = bufc[OBL + (lr + 4) * PST + n];
            mma_f16(acc[0][j], ah[0], bh0, bh1);
            mma_f16(acc[1][j], ah[1], bh0, bh1);
            mma_f16(acc[0][j], ah[0], bl0, bl1);
            mma_f16(acc[1][j], ah[1], bl0, bl1);
            mma_f16(acc[0][j], al[0], bh0, bh1);
            mma_f16(acc[1][j], al[1], bh0, bh1);
        }
        buf_i ^= 1;
    }

    // ---- epilogue ----
    int lr2 = 2 * lr;
    if (packout) {
        int NP = N >> 1;
#pragma unroll
        for (int i = 0; i < 2; i++) {
            int colp = n0 + wn + lr2;
#pragma unroll
            for (int j = 0; j < 8; j++) {
                int col = colp + j * 8;
                if (col >= N) continue;
                int pidx = col >> 1;
                float bi0 = bias[col], bi1 = bias[col + 1];
                int r0 = m0 + wm + i * 16 + lq;
                if (r0 < M) {
                    float v0 = acc[i][j][0] + bi0;
                    float v1 = acc[i][j][1] + bi1;
                    if (relu) { v0 = fmaxf(v0, 0.f); v1 = fmaxf(v1, 0.f); }
                    uint32_t wh, wl;
                    pack_pair(v0, v1, wh, wl);
                    Ch[r0 * NP + pidx] = wh;
                    Cl[r0 * NP + pidx] = wl;
                }
                int r1 = r0 + 8;
                if (r1 < M) {
                    float v0 = acc[i][j][2] + bi0;
                    float v1 = acc[i][j][3] + bi1;
                    if (relu) { v0 = fmaxf(v0, 0.f); v1 = fmaxf(v1, 0.f); }
                    uint32_t wh, wl;
                    pack_pair(v0, v1, wh, wl);
                    Ch[r1 * NP + pidx] = wh;
                    Cl[r1 * NP + pidx] = wl;
                }
            }
        }
    } else {
#pragma unroll
        for (int i = 0; i < 2; i++) {
#pragma unroll
            for (int c = 0; c < 4; c++) {
                int row = m0 + wm + i * 16 + lq + ((c >= 2) ? 8 : 0);
                if (row >= M) continue;
#pragma unroll
                for (int j = 0; j < 8; j++) {
                    int col = n0 + wn + j * 8 + lr2 + (c & 1);
                    if (col >= N) continue;
                    float v = acc[i][j][c] + bias[col];
                    if (relu) v = fmaxf(v, 0.f);
                    C[row * N + col] = v;
                }
            }
        }
    }
}

// ---------------- host orchestration ---------------------------------------
static inline void sgemm(int M, int N, int K, const float* A, const float* B,
                         const float* bias, float* C, uint32_t* Ch, uint32_t* Cl,
                         int relu, int packout) {
    dim3 grid((N + BN - 1) / BN, (M + BM - 1) / BM);
    k_sgemm<<<grid, 256>>>(M, N, K, A, B, bias, C, Ch, Cl, relu, packout);
}

static inline void gemm_f16(int M, int N, int K,
                            const uint32_t* Ah, const uint32_t* Al,
                            const uint32_t* Bh, const uint32_t* Bl,
                            const float* bias, float* C,
                            uint32_t* Ch, uint32_t* Cl, int relu, int packout) {
    dim3 grid((N + GBN - 1) / GBN, (M + GBM - 1) / GBM);
    k_gemm_f16<<<grid, 256>>>(M, N, K, Ah, Al, Bh, Bl, bias, C, Ch, Cl, relu, packout);
}

extern "C" void kernel_launch(void* const* d_in, const int* in_sizes, int n_in,
                              void* d_out, int out_size) {
    const float* x      = (const float*)d_in[0];
    const void*  edges  = d_in[1];
    const void*  batch  = d_in[2];
    const float* w1_0 = (const float*)d_in[3];
    const float* b1_0 = (const float*)d_in[4];
    const float* w2_0 = (const float*)d_in[5];
    const float* b2_0 = (const float*)d_in[6];
    const float* w1_r = (const float*)d_in[7];
    const float* b1_r = (const float*)d_in[8];
    const float* w2_r = (const float*)d_in[9];
    const float* b2_r = (const float*)d_in[10];
    const float* cw1  = (const float*)d_in[11];
    const float* cb1  = (const float*)d_in[12];
    const float* cw2  = (const float*)d_in[13];
    const float* cb2  = (const float*)d_in[14];
    const float* cw3  = (const float*)d_in[15];
    const float* cb3  = (const float*)d_in[16];
    float* out = (float*)d_out;

    float *h, *agg9, *feats, *z1, *z2;
    uint32_t *aggh, *aggl, *t1h, *t1l, *wh, *wl;
    int *src, *dst, *bat, *deg, *rowptr, *cursor, *col, *gptr;
    cudaGetSymbolAddress((void**)&h, g_h);
    cudaGetSymbolAddress((void**)&agg9, g_agg9);
    cudaGetSymbolAddress((void**)&feats, g_feats);
    cudaGetSymbolAddress((void**)&z1, g_z1);
    cudaGetSymbolAddress((void**)&z2, g_z2);
    cudaGetSymbolAddress((void**)&aggh, g_aggh);
    cudaGetSymbolAddress((void**)&aggl, g_aggl);
    cudaGetSymbolAddress((void**)&t1h, g_t1h);
    cudaGetSymbolAddress((void**)&t1l, g_t1l);
    cudaGetSymbolAddress((void**)&wh, g_wh);
    cudaGetSymbolAddress((void**)&wl, g_wl);
    cudaGetSymbolAddress((void**)&src, g_src);
    cudaGetSymbolAddress((void**)&dst, g_dst);
    cudaGetSymbolAddress((void**)&bat, g_batch);
    cudaGetSymbolAddress((void**)&deg, g_deg);
    cudaGetSymbolAddress((void**)&rowptr, g_rowptr);
    cudaGetSymbolAddress((void**)&cursor, g_cursor);
    cudaGetSymbolAddress((void**)&col, g_col);
    cudaGetSymbolAddress((void**)&gptr, g_gptr);

    // 1) index dtype detect + convert
    k_detect<<<1, 32>>>((const unsigned long long*)edges);
    {
        int n = (EE > NN) ? EE : NN;
        k_convert<<<(n + 255) / 256, 256>>>(edges, batch);
    }

    // 2) CSR build + graph ranges + weight packing
    k_zero_int<<<(NN + 255) / 256, 256>>>(deg, NN);
    k_count<<<(EE + 255) / 256, 256>>>(dst, deg);
    k_scan<<<1, 1024>>>(deg, rowptr, cursor, NN);
    k_fill<<<(EE + 255) / 256, 256>>>(src, dst, cursor, col);
    k_gptr<<<(NG + 1 + 255) / 256, 256>>>(bat, gptr);
    {
        int wgrid = (WSZ + 255) / 256;
        k_convw<<<wgrid, 256>>>(w2_0, wh, wl);
        for (int i = 0; i < 4; i++) {
            k_convw<<<wgrid, 256>>>(w1_r + i * HID * HID,
                                    wh + (1 + 2 * i) * WSZ, wl + (1 + 2 * i) * WSZ);
            k_convw<<<wgrid, 256>>>(w2_r + i * HID * HID,
                                    wh + (2 + 2 * i) * WSZ, wl + (2 + 2 * i) * WSZ);
        }
    }

    // 3) layer 0
    k_aggregate<<<NN, 32>>>(x, agg9, rowptr, col, INF);
    sgemm(NN, HID, INF, agg9, w1_0, b1_0, nullptr, t1h, t1l, 1, 1);
    gemm_f16(NN, HID, HID, t1h, t1l, wh, wl, b2_0, h, nullptr, nullptr, 1, 0);

    // 4) layers 1..4
    for (int i = 0; i < 4; i++) {
        k_aggregate_pk<<<NN, 160>>>(h, aggh, aggl, rowptr, col);
        gemm_f16(NN, HID, HID, aggh, aggl,
                 wh + (1 + 2 * i) * WSZ, wl + (1 + 2 * i) * WSZ,
                 b1_r + i * HID, nullptr, t1h, t1l, 1, 1);
        gemm_f16(NN, HID, HID, t1h, t1l,
                 wh + (2 + 2 * i) * WSZ, wl + (2 + 2 * i) * WSZ,
                 b2_r + i * HID, h, nullptr, nullptr, (i < 3) ? 1 : 0, 0);
    }

    // 5) global_add_pool
    k_pool2<<<NG, 160>>>(h, gptr, feats);

    // 6) classifier MLP
    sgemm(NG, CHID, HID, feats, cw1, cb1, z1, nullptr, nullptr, 1, 0);
    sgemm(NG, CHID, CHID, z1, cw2, cb2, z2, nullptr, nullptr, 1, 0);
    sgemm(NG, NT, CHID, z2, cw3, cb3, out, nullptr, nullptr, 0, 0);
}